// round 14
// baseline (speedup 1.0000x reference)
#include <cuda_runtime.h>
#include <math.h>
#include <stdint.h>

#define NB      262144
#define TT      80
#define NSTEP   30
#define RPT     256                 // rows per tile
#define NTILES  (NB / RPT)          // 1024
#define TS      34                  // row stride in floats (8B-aligned cp.async, 2-way LDS)
#define DTC     0.1f
#define GRID    152
#define NBUF    3
#define NCONS   256                 // consumer threads (8 warps)
#define NTHREADS 288                // + 1 producer warp
#define STAGE_V    (RPT * TS)                 // V offset inside stage (floats)
#define STAGE_S    (2 * RPT * TS)             // scalars: [4][RPT]
#define STAGE_ELEMS (2 * RPT * TS + 4 * RPT)  // 18432 floats
#define MB_OFF     (NBUF * STAGE_ELEMS)       // mbarriers after stages (float idx)
#define SMEM_BYTES (MB_OFF * 4 + 64)

__device__ __forceinline__ void cpa8(uint32_t dst, const float* src) {
    asm volatile("cp.async.ca.shared.global [%0], [%1], 8;" :: "r"(dst), "l"(src));
}
__device__ __forceinline__ void cpa4(uint32_t dst, const float* src) {
    asm volatile("cp.async.ca.shared.global [%0], [%1], 4;" :: "r"(dst), "l"(src));
}
__device__ __forceinline__ void mbar_init(uint32_t a, uint32_t cnt) {
    asm volatile("mbarrier.init.shared.b64 [%0], %1;" :: "r"(a), "r"(cnt) : "memory");
}
__device__ __forceinline__ void mbar_arrive(uint32_t a) {
    asm volatile("mbarrier.arrive.shared.b64 _, [%0];" :: "r"(a) : "memory");
}
__device__ __forceinline__ void cpasync_mbar_arrive_noinc(uint32_t a) {
    // .noinc: this thread's async-completion CONSUMES one expected arrival
    // (default variant is net-zero and would deadlock a count-N barrier).
    asm volatile("cp.async.mbarrier.arrive.noinc.shared.b64 [%0];" :: "r"(a) : "memory");
}
__device__ __forceinline__ void mbar_wait(uint32_t a, uint32_t parity) {
    asm volatile(
        "{\n\t.reg .pred P;\n\t"
        "WL_%=:\n\t"
        "mbarrier.try_wait.parity.acquire.cta.shared::cta.b64 P, [%0], %1, 0x989680;\n\t"
        "@P bra.uni WD_%=;\n\t"
        "bra.uni WL_%=;\n\t"
        "WD_%=:\n\t}"
        :: "r"(a), "r"(parity) : "memory");
}

__global__ __launch_bounds__(NTHREADS, 1)
void traj_kernel(const float* __restrict__ params,
                 const float* __restrict__ sv_v,
                 const float* __restrict__ hh,
                 const float* __restrict__ dvv,
                 const float* __restrict__ svY,
                 const float* __restrict__ lvY,
                 const float* __restrict__ lvv,
                 float* __restrict__ out)
{
    extern __shared__ float smem[];   // [NBUF][STAGE_ELEMS] + mbarriers
    const int tid  = threadIdx.x;
    const int lane = tid & 31;
    const uint32_t smem_u32 = (uint32_t)__cvta_generic_to_shared(smem);
    const uint32_t mb = smem_u32 + (uint32_t)MB_OFF * 4u;   // full[s]=mb+s*16, empty[s]=+8

    if (tid == 0) {
        #pragma unroll
        for (int s = 0; s < NBUF; ++s) {
            mbar_init(mb + s * 16,     32);    // full: 32 producer-lane async arrivals (.noinc)
            mbar_init(mb + s * 16 + 8, NCONS); // empty: all consumer threads
        }
    }
    __syncthreads();

    if (tid >= NCONS) {
        // ================= PRODUCER WARP =================
        int ps = 0, pph = 1;    // empty-wait parity starts 1: first NBUF waits pass
        for (int t = blockIdx.x; t < NTILES; t += (int)gridDim.x) {
            mbar_wait(mb + ps * 16 + 8, (uint32_t)pph);   // stage free?
            const int r0 = t * RPT;
            const uint32_t base = smem_u32 + (uint32_t)(ps * STAGE_ELEMS) * 4u;
            // lv tiles: 256 rows x 16 8B-chunks x 2 arrays = 4096 chunks / 32 lanes
            // = 128 iterations.
            #pragma unroll 4
            for (int k = 0; k < 128; ++k) {
                int idx = k * 32 + lane;
                int row = idx >> 4;          // 0..255
                int c   = idx & 15;          // 0..15
                size_t g = (size_t)(r0 + row) * TT + 48 + c * 2;
                uint32_t dY = base + (uint32_t)(row * TS + c * 2) * 4u;
                cpa8(dY, lvY + g);
                cpa8(dY + (uint32_t)STAGE_V * 4u, lvv + g);
            }
            // scalars: 4 arrays x 256 rows, 4B each.
            #pragma unroll
            for (int k = 0; k < 8; ++k) {
                int row = k * 32 + lane;
                size_t g = (size_t)(r0 + row) * TT + 49;
                uint32_t dS = base + (uint32_t)(STAGE_S + row) * 4u;
                cpa4(dS,                          sv_v + g);
                cpa4(dS + (uint32_t)RPT * 4u,     hh   + g);
                cpa4(dS + (uint32_t)(2*RPT) * 4u, dvv  + g);
                cpa4(dS + (uint32_t)(3*RPT) * 4u, svY  + g);
            }
            cpasync_mbar_arrive_noinc(mb + ps * 16);  // full[ps]: arrives when lane's copies land
            if (++ps == NBUF) { ps = 0; pph ^= 1; }
        }
    } else {
        // ================= CONSUMER WARPS =================
        const int wid   = tid >> 5;
        const int wrow0 = wid * 32;

        const float s0  = __ldg(params + 0);
        const float Thw = __ldg(params + 1);
        const float pa  = __ldg(params + 2);
        const float pb  = __ldg(params + 3);
        const float v0  = __ldg(params + 4);
        const float inv_c2 = 1.0f / (2.0f * sqrtf(pa * pb));
        const float inv_v0 = 1.0f / v0;

        int cs = 0, cph = 0;
        for (int t = blockIdx.x; t < NTILES; t += (int)gridDim.x) {
            mbar_wait(mb + cs * 16, (uint32_t)cph);   // stage full?

            float* base = smem + cs * STAGE_ELEMS;
            float* myY  = base + tid * TS + 2;        // element 50 = index 2
            const float* myV = myY + STAGE_V;
            const float* sS  = base + STAGE_S;

            float v   = sS[tid];
            float gap = sS[RPT + tid];
            float dvl = sS[2 * RPT + tid];
            float y   = sS[3 * RPT + tid];

            #pragma unroll
            for (int i = 0; i < NSTEP; ++i) {
                // s_star = s0 + max(v*Thw + v*dv/(2*sqrt(a*b)), 0)  (NaN-prop max)
                float tt     = v * Thw + (v * dvl) * inv_c2;
                float relu   = !(tt <= 0.0f) ? tt : 0.0f;
                float s_star = s0 + relu;

                float rv  = v * inv_v0;
                float rv2 = rv * rv;
                float rs  = __fdividef(s_star, gap);
                float a_calc = pa * (1.0f - rv2 * rv2 - rs * rs);

                float v2  = v + a_calc * DTC;
                // where(v2 <= 0, -v/DT, a_calc); 1/0.1f == 10.0f exactly
                float a_t = (v2 <= 0.0f) ? (-v * 10.0f) : a_calc;

                v   = v + a_t * DTC;
                dvl = v - myV[i];
                y   = y + v * DTC;
                gap = myY[i] - y;     // last read of lv_Y slot i ...
                myY[i] = y;           // ... reuse as output staging
            }
            __syncwarp();

            // Warp-private coalesced writeback: 960 contiguous floats.
            const size_t obase = (size_t)(t * RPT + wrow0) * NSTEP;
            const float* wO = base + wrow0 * TS;
            #pragma unroll
            for (int k = 0; k < NSTEP; ++k) {
                int idx = k * 32 + lane;
                int r   = idx / NSTEP;
                int c   = idx - r * NSTEP;
                out[obase + idx] = wO[r * TS + 2 + c];
            }
            __syncwarp();
            mbar_arrive(mb + cs * 16 + 8);    // release stage
            if (++cs == NBUF) { cs = 0; cph ^= 1; }
        }
    }
}

extern "C" void kernel_launch(void* const* d_in, const int* in_sizes, int n_in,
                              void* d_out, int out_size) {
    const float* params = (const float*)d_in[0];
    const float* sv_v1  = (const float*)d_in[1];
    const float* h1     = (const float*)d_in[2];
    const float* dv1    = (const float*)d_in[3];
    const float* sv_Y1  = (const float*)d_in[4];
    const float* lvY    = (const float*)d_in[5];
    const float* lvv    = (const float*)d_in[6];
    float* out = (float*)d_out;

    cudaFuncSetAttribute(traj_kernel,
                         cudaFuncAttributeMaxDynamicSharedMemorySize,
                         (int)SMEM_BYTES);
    traj_kernel<<<GRID, NTHREADS, SMEM_BYTES>>>(params, sv_v1, h1, dv1, sv_Y1,
                                                lvY, lvv, out);
}

// round 15
// speedup vs baseline: 1.0066x; 1.0066x over previous
#include <cuda_runtime.h>
#include <math.h>
#include <stdint.h>

#define NB      262144
#define TT      80
#define NSTEP   30
#define RPT     256               // rows per tile (= threads per block)
#define NTILES  (NB / RPT)        // 1024
#define TS      34                // row stride in floats (8B-aligned cp.async, 2-way LDS)
#define DTC     0.1f
#define GRID    152               // persistent: 1 CTA per SM
#define BUFELEMS (2 * RPT * TS)   // Y + V for one buffer (floats)
#define SMEM_BYTES (3 * BUFELEMS * sizeof(float))   // 208896 B

__device__ __forceinline__ void cpa8(uint32_t dst, const float* src) {
    asm volatile("cp.async.ca.shared.global [%0], [%1], 8;" :: "r"(dst), "l"(src));
}

struct Sc { float v, g, d, y; };

__global__ __launch_bounds__(RPT, 1)
void traj_kernel(const float* __restrict__ params,
                 const float* __restrict__ sv_v,
                 const float* __restrict__ hh,
                 const float* __restrict__ dvv,
                 const float* __restrict__ svY,
                 const float* __restrict__ lvY,
                 const float* __restrict__ lvv,
                 float* __restrict__ out)
{
    extern __shared__ float smem[];      // [3][{Y,V}][RPT][TS]
    const int tid   = threadIdx.x;
    const int wid   = tid >> 5;
    const int lane  = tid & 31;
    const int wrow0 = wid * 32;
    const uint32_t smem_u32 = (uint32_t)__cvta_generic_to_shared(smem);
    const int G = (int)gridDim.x;

    const float s0  = __ldg(params + 0);
    const float Thw = __ldg(params + 1);
    const float pa  = __ldg(params + 2);
    const float pb  = __ldg(params + 3);
    const float v0  = __ldg(params + 4);
    const float inv_c2 = 1.0f / (2.0f * sqrtf(pa * pb));
    const float inv_v0 = 1.0f / v0;

    // Stage this warp's 32 rows of tile `tt` into the buffer at byte offset ob.
    auto stage = [&](int tt, uint32_t ob) {
        const int r0 = tt * RPT;
        #pragma unroll
        for (int k = 0; k < 16; ++k) {
            int idx = k * 32 + lane;
            int row = wrow0 + (idx >> 4);
            int c   = idx & 15;
            size_t g = (size_t)(r0 + row) * TT + 48 + c * 2;
            uint32_t dY = smem_u32 + ob + (uint32_t)(row * TS + c * 2) * 4u;
            cpa8(dY, lvY + g);
            cpa8(dY + (uint32_t)(RPT * TS) * 4u, lvv + g);
        }
    };
    auto ldsc = [&](int tt) {
        size_t sb = (size_t)(tt * RPT + tid) * TT + 49;
        Sc s;
        s.v = __ldg(sv_v + sb); s.g = __ldg(hh + sb);
        s.d = __ldg(dvv  + sb); s.y = __ldg(svY + sb);
        return s;
    };
    auto compute = [&](int tt, float* bY, Sc s) {
        float v = s.v, gap = s.g, dvl = s.d, y = s.y;
        float* myY = bY + tid * TS + 2;          // element 50 = index 2
        const float* myV = myY + RPT * TS;
        #pragma unroll
        for (int i = 0; i < NSTEP; ++i) {
            float t2     = v * Thw + (v * dvl) * inv_c2;
            float relu   = !(t2 <= 0.0f) ? t2 : 0.0f;   // NaN-propagating max(.,0)
            float s_star = s0 + relu;
            float rv  = v * inv_v0;
            float rv2 = rv * rv;
            float rs  = __fdividef(s_star, gap);
            float a_calc = pa * (1.0f - rv2 * rv2 - rs * rs);
            float v2  = v + a_calc * DTC;
            float a_t = (v2 <= 0.0f) ? (-v * 10.0f) : a_calc;  // 1/0.1f == 10.0f
            v   = v + a_t * DTC;
            dvl = v - myV[i];
            y   = y + v * DTC;
            gap = myY[i] - y;     // last read of slot i ...
            myY[i] = y;           // ... reuse as output staging
        }
        __syncwarp();
        const size_t obase = (size_t)(tt * RPT + wrow0) * NSTEP;
        const float* wO = bY + wrow0 * TS;
        #pragma unroll
        for (int k = 0; k < NSTEP; ++k) {
            int idx = k * 32 + lane;
            int r   = idx / NSTEP;
            int c   = idx - r * NSTEP;
            __stcs(out + obase + idx, wO[r * TS + 2 + c]);
        }
        __syncwarp();
    };

    float* const b0 = smem;
    float* const b1 = smem + BUFELEMS;
    float* const b2 = smem + 2 * BUFELEMS;
    const uint32_t ob0 = 0, ob1 = (uint32_t)BUFELEMS * 4u, ob2 = (uint32_t)(2 * BUFELEMS) * 4u;

    int t0 = blockIdx.x;
    Sc sc0{}, sc1{}, sc2{};

    // ---- Prologue: two groups in flight before first compute. ----
    stage(t0, ob0);
    asm volatile("cp.async.commit_group;");
    sc0 = ldsc(t0);
    if (t0 + G < NTILES) { stage(t0 + G, ob1); sc1 = ldsc(t0 + G); }
    asm volatile("cp.async.commit_group;");

    // ---- Main loop: 3 tiles per iteration, constant buffer offsets. ----
    while (t0 < NTILES) {
        const int t1 = t0 + G, t2t = t0 + 2 * G;

        if (t2t < NTILES) { stage(t2t, ob2); sc2 = ldsc(t2t); }
        asm volatile("cp.async.commit_group;");
        asm volatile("cp.async.wait_group 2;");
        __syncwarp();
        compute(t0, b0, sc0);

        if (t1 < NTILES) {
            const int t3 = t0 + 3 * G;
            if (t3 < NTILES) { stage(t3, ob0); sc0 = ldsc(t3); }
            asm volatile("cp.async.commit_group;");
            asm volatile("cp.async.wait_group 2;");
            __syncwarp();
            compute(t1, b1, sc1);
        }
        if (t2t < NTILES) {
            const int t4 = t0 + 4 * G;
            if (t4 < NTILES) { stage(t4, ob1); sc1 = ldsc(t4); }
            asm volatile("cp.async.commit_group;");
            asm volatile("cp.async.wait_group 2;");
            __syncwarp();
            compute(t2t, b2, sc2);
        }
        t0 += 3 * G;
    }
}

extern "C" void kernel_launch(void* const* d_in, const int* in_sizes, int n_in,
                              void* d_out, int out_size) {
    const float* params = (const float*)d_in[0];
    const float* sv_v1  = (const float*)d_in[1];
    const float* h1     = (const float*)d_in[2];
    const float* dv1    = (const float*)d_in[3];
    const float* sv_Y1  = (const float*)d_in[4];
    const float* lvY    = (const float*)d_in[5];
    const float* lvv    = (const float*)d_in[6];
    float* out = (float*)d_out;

    cudaFuncSetAttribute(traj_kernel,
                         cudaFuncAttributeMaxDynamicSharedMemorySize,
                         (int)SMEM_BYTES);
    traj_kernel<<<GRID, RPT, SMEM_BYTES>>>(params, sv_v1, h1, dv1, sv_Y1,
                                           lvY, lvv, out);
}

// round 16
// speedup vs baseline: 1.0124x; 1.0057x over previous
#include <cuda_runtime.h>
#include <math.h>
#include <stdint.h>

#define NB      262144
#define TT      80
#define NSTEP   30
#define RPT     128               // rows per tile = threads per block (4 warps)
#define NTILES  (NB / RPT)        // 2048 full tiles
#define TS      34                // row stride in floats (8B-aligned cp.async, 2-way LDS)
#define DTC     0.1f
#define GRID    304               // persistent: 2 CTAs per SM on 152-SM GB300
#define BUFELEMS (2 * RPT * TS)   // Y + V for one buffer (floats)
#define SMEM_BYTES (2 * BUFELEMS * sizeof(float))   // 69632 B -> 2 CTAs/SM fit

__device__ __forceinline__ void cpa8(uint32_t dst, const float* src) {
    asm volatile("cp.async.ca.shared.global [%0], [%1], 8;" :: "r"(dst), "l"(src));
}

// (128, 2): reg budget = 65536/256 = 256 regs/thread — zero pressure on the
// batched-LDG schedule (R7 uses 158). Two independent CTAs per SM phase-shift
// their stage/compute pulses against each other.
__global__ __launch_bounds__(RPT, 2)
void traj_kernel(const float* __restrict__ params,
                 const float* __restrict__ sv_v,
                 const float* __restrict__ hh,
                 const float* __restrict__ dvv,
                 const float* __restrict__ svY,
                 const float* __restrict__ lvY,
                 const float* __restrict__ lvv,
                 float* __restrict__ out)
{
    extern __shared__ float smem[];      // [2][{Y,V}][RPT][TS]
    const int tid   = threadIdx.x;
    const int wid   = tid >> 5;
    const int lane  = tid & 31;
    const int wrow0 = wid * 32;
    const uint32_t smem_u32 = (uint32_t)__cvta_generic_to_shared(smem);

    // Params: broadcast, L1-resident.
    const float s0  = __ldg(params + 0);
    const float Thw = __ldg(params + 1);
    const float pa  = __ldg(params + 2);
    const float pb  = __ldg(params + 3);
    const float v0  = __ldg(params + 4);
    const float inv_c2 = 1.0f / (2.0f * sqrtf(pa * pb));
    const float inv_v0 = 1.0f / v0;

    int t   = blockIdx.x;
    int buf = 0;
    float nv = 0.f, ngap = 0.f, ndvl = 0.f, ny = 0.f;

    // ---- Prologue: async-stage tile t into buffer 0, prefetch its scalars. ----
    {
        const int r0 = t * RPT;
        // Warp stages its 32 rows: 32 rows x 16 8B-chunks = 512 = 16 iters x 32 lanes.
        #pragma unroll
        for (int k = 0; k < 16; ++k) {
            int idx = k * 32 + lane;
            int row = wrow0 + (idx >> 4);   // 16 8B-chunks per row
            int c   = idx & 15;
            size_t g = (size_t)(r0 + row) * TT + 48 + c * 2;
            uint32_t dY = smem_u32 + (uint32_t)(row * TS + c * 2) * 4u;
            cpa8(dY, lvY + g);
            cpa8(dY + (uint32_t)(RPT * TS) * 4u, lvv + g);
        }
        asm volatile("cp.async.commit_group;");
        size_t sb = (size_t)(r0 + tid) * TT + 49;
        nv   = __ldg(sv_v + sb);
        ngap = __ldg(hh   + sb);
        ndvl = __ldg(dvv  + sb);
        ny   = __ldg(svY  + sb);
    }

    while (t < NTILES) {
        const int tn = t + (int)gridDim.x;
        float v = nv, gap = ngap, dvl = ndvl, y = ny;

        if (tn < NTILES) {
            // ---- Issue next tile's loads into the other buffer (overlaps compute). ----
            const int r0n = tn * RPT;
            const uint32_t ob = (uint32_t)((buf ^ 1) * BUFELEMS) * 4u;
            #pragma unroll
            for (int k = 0; k < 16; ++k) {
                int idx = k * 32 + lane;
                int row = wrow0 + (idx >> 4);
                int c   = idx & 15;
                size_t g = (size_t)(r0n + row) * TT + 48 + c * 2;
                uint32_t dY = smem_u32 + ob + (uint32_t)(row * TS + c * 2) * 4u;
                cpa8(dY, lvY + g);
                cpa8(dY + (uint32_t)(RPT * TS) * 4u, lvv + g);
            }
            asm volatile("cp.async.commit_group;");
            size_t sb = (size_t)(r0n + tid) * TT + 49;
            nv   = __ldg(sv_v + sb);
            ngap = __ldg(hh   + sb);
            ndvl = __ldg(dvv  + sb);
            ny   = __ldg(svY  + sb);
            asm volatile("cp.async.wait_group 1;");  // tile t's group done; tn in flight
        } else {
            asm volatile("cp.async.wait_group 0;");
        }
        __syncwarp();

        // ---- Compute this warp's 32 rows from buffer `buf`. ----
        float* bY  = smem + buf * BUFELEMS;
        float* myY = bY + tid * TS + 2;          // element 50 = tile index 2
        const float* myV = myY + RPT * TS;

        #pragma unroll
        for (int i = 0; i < NSTEP; ++i) {
            // s_star = s0 + max(v*Thw + v*dv/(2*sqrt(a*b)), 0)  (NaN-propagating max)
            float tt     = v * Thw + (v * dvl) * inv_c2;
            float relu   = !(tt <= 0.0f) ? tt : 0.0f;
            float s_star = s0 + relu;

            float rv  = v * inv_v0;
            float rv2 = rv * rv;
            float rs  = __fdividef(s_star, gap);
            float a_calc = pa * (1.0f - rv2 * rv2 - rs * rs);

            float v2  = v + a_calc * DTC;
            // where(v2 <= 0, -v/DT, a_calc); 1/0.1f rounds to exactly 10.0f
            float a_t = (v2 <= 0.0f) ? (-v * 10.0f) : a_calc;

            v   = v + a_t * DTC;
            dvl = v - myV[i];
            y   = y + v * DTC;
            gap = myY[i] - y;     // last read of lv_Y slot i ...
            myY[i] = y;           // ... reuse it to stage the output in place
        }
        __syncwarp();

        // ---- Warp-private coalesced writeback: 960 contiguous floats. ----
        const size_t obase = (size_t)(t * RPT + wrow0) * NSTEP;
        const float* wO = bY + wrow0 * TS;
        #pragma unroll
        for (int k = 0; k < NSTEP; ++k) {
            int idx = k * 32 + lane;
            int row = idx / NSTEP;
            int col = idx - row * NSTEP;
            out[obase + idx] = wO[row * TS + 2 + col];
        }
        __syncwarp();   // SMEM reads done before this buffer is refilled

        buf ^= 1;
        t = tn;
    }
}

extern "C" void kernel_launch(void* const* d_in, const int* in_sizes, int n_in,
                              void* d_out, int out_size) {
    const float* params = (const float*)d_in[0];
    const float* sv_v1  = (const float*)d_in[1];
    const float* h1     = (const float*)d_in[2];
    const float* dv1    = (const float*)d_in[3];
    const float* sv_Y1  = (const float*)d_in[4];
    const float* lvY    = (const float*)d_in[5];
    const float* lvv    = (const float*)d_in[6];
    float* out = (float*)d_out;

    cudaFuncSetAttribute(traj_kernel,
                         cudaFuncAttributeMaxDynamicSharedMemorySize,
                         (int)SMEM_BYTES);
    traj_kernel<<<GRID, RPT, SMEM_BYTES>>>(params, sv_v1, h1, dv1, sv_Y1,
                                           lvY, lvv, out);
}

// round 17
// speedup vs baseline: 1.4466x; 1.4290x over previous
#include <cuda_runtime.h>
#include <math.h>
#include <stdint.h>

#define NB      262144
#define TT      80
#define NSTEP   30
#define RPT     256               // rows (threads) per block / per tile
#define NTILES  (NB / RPT)        // 1024
#define TS      34                // tile row stride in floats (8B-aligned cp.async, 2-way LDS)
#define DTC     0.1f
#define GRID    152               // persistent: 1 CTA per SM on GB300
#define SC_OFF  (2 * RPT * TS)    // scalar region offset in a buffer (floats): [4][RPT][4]
#define BUFELEMS (2 * RPT * TS + 16 * RPT)   // lv_Y + lv_v + scalars, one buffer
#define SMEM_BYTES (2 * BUFELEMS * sizeof(float))   // 172032 B

__device__ __forceinline__ void cpa8(uint32_t dst, const float* src) {
    asm volatile("cp.async.ca.shared.global [%0], [%1], 8;" :: "r"(dst), "l"(src));
}
// .cg: L2-only 16B transfer — the small-request path for the scalar gathers.
__device__ __forceinline__ void cpa16cg(uint32_t dst, const float* src) {
    asm volatile("cp.async.cg.shared.global [%0], [%1], 16;" :: "r"(dst), "l"(src));
}

__global__ __launch_bounds__(RPT, 1)
void traj_kernel(const float* __restrict__ params,
                 const float* __restrict__ sv_v,
                 const float* __restrict__ hh,
                 const float* __restrict__ dvv,
                 const float* __restrict__ svY,
                 const float* __restrict__ lvY,
                 const float* __restrict__ lvv,
                 float* __restrict__ out)
{
    extern __shared__ float smem[];      // [2][ lvY | lvv | scalars ]
    const int tid   = threadIdx.x;
    const int wid   = tid >> 5;
    const int lane  = tid & 31;
    const int wrow0 = wid * 32;
    const uint32_t smem_u32 = (uint32_t)__cvta_generic_to_shared(smem);

    // Params: broadcast, L1-resident.
    const float s0  = __ldg(params + 0);
    const float Thw = __ldg(params + 1);
    const float pa  = __ldg(params + 2);
    const float pb  = __ldg(params + 3);
    const float v0  = __ldg(params + 4);
    const float inv_c2 = 1.0f / (2.0f * sqrtf(pa * pb));
    const float inv_v0 = 1.0f / v0;

    // Stage tile `tt` into buffer at byte offset ob: this warp's 32 lv rows
    // (16 8B-chunks x 2 arrays) + this THREAD's 4 scalar 16B chunks.
    auto stage = [&](int tt, uint32_t ob) {
        const int r0 = tt * RPT;
        #pragma unroll
        for (int k = 0; k < 16; ++k) {
            int idx = k * 32 + lane;
            int row = wrow0 + (idx >> 4);
            int c   = idx & 15;
            size_t g = (size_t)(r0 + row) * TT + 48 + c * 2;
            uint32_t dY = smem_u32 + ob + (uint32_t)(row * TS + c * 2) * 4u;
            cpa8(dY, lvY + g);
            cpa8(dY + (uint32_t)(RPT * TS) * 4u, lvv + g);
        }
        // Scalars: bytes 192..208 of own row (16B-aligned; element 49 = slot 1).
        size_t gs = (size_t)(r0 + tid) * TT + 48;
        uint32_t dS = smem_u32 + ob + (uint32_t)(SC_OFF + tid * 4) * 4u;
        cpa16cg(dS,                     sv_v + gs);
        cpa16cg(dS + RPT * 16u,         hh   + gs);
        cpa16cg(dS + 2u * RPT * 16u,    dvv  + gs);
        cpa16cg(dS + 3u * RPT * 16u,    svY  + gs);
    };

    int t   = blockIdx.x;
    int buf = 0;

    // ---- Prologue: stage tile t into buffer 0. ----
    stage(t, 0);
    asm volatile("cp.async.commit_group;");

    while (t < NTILES) {
        const int tn = t + (int)gridDim.x;

        if (tn < NTILES) {
            stage(tn, (uint32_t)((buf ^ 1) * BUFELEMS) * 4u);
            asm volatile("cp.async.commit_group;");
            asm volatile("cp.async.wait_group 1;");  // tile t's group done; tn in flight
        } else {
            asm volatile("cp.async.wait_group 0;");
        }
        __syncwarp();

        // ---- Compute this warp's 32 rows from buffer `buf`. ----
        float* bY  = smem + buf * BUFELEMS;
        float* myY = bY + tid * TS + 2;          // element 50 = tile index 2
        const float* myV = myY + RPT * TS;
        const float* sS  = bY + SC_OFF;

        float v   = sS[tid * 4 + 1];
        float gap = sS[RPT * 4 + tid * 4 + 1];
        float dvl = sS[2 * RPT * 4 + tid * 4 + 1];
        float y   = sS[3 * RPT * 4 + tid * 4 + 1];

        #pragma unroll
        for (int i = 0; i < NSTEP; ++i) {
            // s_star = s0 + max(v*Thw + v*dv/(2*sqrt(a*b)), 0)  (NaN-propagating max)
            float tt2    = v * Thw + (v * dvl) * inv_c2;
            float relu   = !(tt2 <= 0.0f) ? tt2 : 0.0f;
            float s_star = s0 + relu;

            float rv  = v * inv_v0;
            float rv2 = rv * rv;
            float rs  = __fdividef(s_star, gap);
            float a_calc = pa * (1.0f - rv2 * rv2 - rs * rs);

            float v2  = v + a_calc * DTC;
            // where(v2 <= 0, -v/DT, a_calc); 1/0.1f rounds to exactly 10.0f
            float a_t = (v2 <= 0.0f) ? (-v * 10.0f) : a_calc;

            v   = v + a_t * DTC;
            dvl = v - myV[i];
            y   = y + v * DTC;
            gap = myY[i] - y;     // last read of lv_Y slot i ...
            myY[i] = y;           // ... reuse it to stage the output in place
        }
        __syncwarp();

        // ---- Warp-private coalesced writeback: 960 contiguous floats. ----
        const size_t obase = (size_t)(t * RPT + wrow0) * NSTEP;
        const float* wO = bY + wrow0 * TS;
        #pragma unroll
        for (int k = 0; k < NSTEP; ++k) {
            int idx = k * 32 + lane;
            int row = idx / NSTEP;
            int col = idx - row * NSTEP;
            out[obase + idx] = wO[row * TS + 2 + col];
        }
        __syncwarp();   // SMEM reads done before this buffer is refilled next iteration

        buf ^= 1;
        t = tn;
    }
}

extern "C" void kernel_launch(void* const* d_in, const int* in_sizes, int n_in,
                              void* d_out, int out_size) {
    const float* params = (const float*)d_in[0];
    const float* sv_v1  = (const float*)d_in[1];
    const float* h1     = (const float*)d_in[2];
    const float* dv1    = (const float*)d_in[3];
    const float* sv_Y1  = (const float*)d_in[4];
    const float* lvY    = (const float*)d_in[5];
    const float* lvv    = (const float*)d_in[6];
    float* out = (float*)d_out;

    cudaFuncSetAttribute(traj_kernel,
                         cudaFuncAttributeMaxDynamicSharedMemorySize,
                         (int)SMEM_BYTES);
    traj_kernel<<<GRID, RPT, SMEM_BYTES>>>(params, sv_v1, h1, dv1, sv_Y1,
                                           lvY, lvv, out);
}